// round 1
// baseline (speedup 1.0000x reference)
#include <cuda_runtime.h>

#define T_SEQ 2048
#define NB    2
#define NH    16
#define NKV   2
#define HD    128
#define DIM   2048

// Scratch (allocation-free rule: __device__ globals)
__device__ float g_q[NB * T_SEQ * DIM];          // [B,T,16,128]
__device__ float g_k[NB * T_SEQ * NKV * HD];     // [B,T,2,128]
__device__ float g_v[NB * T_SEQ * NKV * HD];     // [B,T,2,128]
__device__ float g_attn[NB * T_SEQ * DIM];       // [B,T,16,128]

// ---------------------------------------------------------------------------
// SGEMM: C[M,N] = A[M,K] @ B[K,N] (+ bias[N]).  128x128 tile, BK=8, 8x8 micro.
// 256 threads.
// ---------------------------------------------------------------------------
__global__ void sgemm_bias_kernel(const float* __restrict__ A,
                                  const float* __restrict__ Bw,
                                  const float* __restrict__ bias,
                                  float* __restrict__ C,
                                  int M, int N, int K)
{
    __shared__ float As[8][128];
    __shared__ float Bs[8][128];

    const int tid = threadIdx.x;
    const int tx  = tid & 15;       // 0..15  -> N dir
    const int ty  = tid >> 4;       // 0..15  -> M dir
    const int rowBase = blockIdx.y * 128;
    const int colBase = blockIdx.x * 128;

    float acc[8][8];
#pragma unroll
    for (int i = 0; i < 8; i++)
#pragma unroll
        for (int j = 0; j < 8; j++) acc[i][j] = 0.f;

    const int aRow = tid >> 1;            // 0..127
    const int aCol = (tid & 1) * 4;       // 0 or 4
    const int bRow = tid >> 5;            // 0..7
    const int bCol = (tid & 31) * 4;      // 0..124

    const float* Ap = A  + (size_t)rowBase * K;
    const float* Bp = Bw + colBase;

    for (int k0 = 0; k0 < K; k0 += 8) {
        float4 a4 = *(const float4*)(Ap + (size_t)aRow * K + k0 + aCol);
        As[aCol + 0][aRow] = a4.x;
        As[aCol + 1][aRow] = a4.y;
        As[aCol + 2][aRow] = a4.z;
        As[aCol + 3][aRow] = a4.w;
        float4 b4 = *(const float4*)(Bp + (size_t)(k0 + bRow) * N + bCol);
        *(float4*)&Bs[bRow][bCol] = b4;
        __syncthreads();

#pragma unroll
        for (int kk = 0; kk < 8; kk++) {
            float4 a0 = *(const float4*)&As[kk][ty * 8];
            float4 a1 = *(const float4*)&As[kk][ty * 8 + 4];
            float4 b0 = *(const float4*)&Bs[kk][tx * 8];
            float4 b1 = *(const float4*)&Bs[kk][tx * 8 + 4];
            float ar[8] = {a0.x, a0.y, a0.z, a0.w, a1.x, a1.y, a1.z, a1.w};
            float br[8] = {b0.x, b0.y, b0.z, b0.w, b1.x, b1.y, b1.z, b1.w};
#pragma unroll
            for (int i = 0; i < 8; i++)
#pragma unroll
                for (int j = 0; j < 8; j++)
                    acc[i][j] += ar[i] * br[j];
        }
        __syncthreads();
    }

#pragma unroll
    for (int i = 0; i < 8; i++) {
        int r = rowBase + ty * 8 + i;
#pragma unroll
        for (int j = 0; j < 8; j += 4) {
            int c = colBase + tx * 8 + j;
            float4 o;
            o.x = acc[i][j + 0]; o.y = acc[i][j + 1];
            o.z = acc[i][j + 2]; o.w = acc[i][j + 3];
            if (bias) {
                o.x += bias[c + 0]; o.y += bias[c + 1];
                o.z += bias[c + 2]; o.w += bias[c + 3];
            }
            *(float4*)(C + (size_t)r * N + c) = o;
        }
    }
}

// ---------------------------------------------------------------------------
// RoPE in-place on q [B,T,16,128] and k [B,T,2,128].
// One thread per (b,t,head,pair).  18 = 16 q heads + 2 kv heads.
// ---------------------------------------------------------------------------
__global__ void rope_kernel(float* __restrict__ q, float* __restrict__ k,
                            const float* __restrict__ cosT,
                            const float* __restrict__ sinT)
{
    int idx = blockIdx.x * blockDim.x + threadIdx.x;
    int i   = idx & 63;  idx >>= 6;
    int h   = idx % 18;  idx /= 18;
    int t   = idx % T_SEQ;
    int b   = idx / T_SEQ;
    if (b >= NB) return;

    float c0 = cosT[t * HD + i];
    float s0 = sinT[t * HD + i];
    float c1 = cosT[t * HD + i + 64];
    float s1 = sinT[t * HD + i + 64];

    float* base;
    if (h < NH) base = q + ((size_t)(b * T_SEQ + t) * NH  + h)        * HD;
    else        base = k + ((size_t)(b * T_SEQ + t) * NKV + (h - NH)) * HD;

    float x1 = base[i];
    float x2 = base[i + 64];
    base[i]      = x1 * c0 - x2 * s0;
    base[i + 64] = x2 * c1 + x1 * s1;
}

// ---------------------------------------------------------------------------
// Flash attention fp32.  Block = 64 q rows x one head x one batch.
// 256 threads = 16x16 grid; each thread: 4x4 of S, 4 rows x 8 cols of O.
// ---------------------------------------------------------------------------
#define PS_STRIDE 68

__global__ void attn_kernel(const float* __restrict__ q,
                            const float* __restrict__ k,
                            const float* __restrict__ v,
                            float* __restrict__ o)
{
    extern __shared__ float sm[];
    float* Qt = sm;                   // [128][64]  (d-major, transposed)
    float* Kt = Qt + HD * 64;         // [128][64]
    float* Vs = Kt + HD * 64;         // [64][128]  (row-major)
    float* Ps = Vs + 64 * HD;         // [64][PS_STRIDE]

    const int qb  = blockIdx.x;
    const int h   = blockIdx.y;
    const int b   = blockIdx.z;
    const int kvh = h >> 3;           // 16/2 = 8 q heads per kv head
    const int tid = threadIdx.x;
    const int tx  = tid & 15;
    const int ty  = tid >> 4;
    const int q0  = qb * 64;
    const float scale = 0.0883883476483184405f;  // 1/sqrt(128)

    // Load Q tile transposed: Qt[d][r]
    const float* qp = q + ((size_t)(b * T_SEQ + q0) * NH + h) * HD;
#pragma unroll
    for (int it = 0; it < 8; it++) {
        int lin = tid + it * 256;          // float4 index, 0..2047
        int r   = lin >> 5;                // 0..63
        int c4  = (lin & 31) << 2;         // 0..124
        float4 t4 = *(const float4*)(qp + (size_t)r * DIM + c4);
        Qt[(c4 + 0) * 64 + r] = t4.x;
        Qt[(c4 + 1) * 64 + r] = t4.y;
        Qt[(c4 + 2) * 64 + r] = t4.z;
        Qt[(c4 + 3) * 64 + r] = t4.w;
    }

    float m_i[4], l_i[4], acc[4][8];
#pragma unroll
    for (int i = 0; i < 4; i++) {
        m_i[i] = -1e30f; l_i[i] = 0.f;
#pragma unroll
        for (int u = 0; u < 8; u++) acc[i][u] = 0.f;
    }

    for (int kt = 0; kt <= qb; kt++) {
        const int kb0 = kt * 64;
        __syncthreads();   // protect Kt/Vs/Ps from previous iteration readers

        const float* kp = k + ((size_t)(b * T_SEQ + kb0) * NKV + kvh) * HD;
        const float* vp = v + ((size_t)(b * T_SEQ + kb0) * NKV + kvh) * HD;
#pragma unroll
        for (int it = 0; it < 8; it++) {
            int lin = tid + it * 256;
            int r   = lin >> 5;
            int c4  = (lin & 31) << 2;
            float4 t4 = *(const float4*)(kp + (size_t)r * (NKV * HD) + c4);
            Kt[(c4 + 0) * 64 + r] = t4.x;
            Kt[(c4 + 1) * 64 + r] = t4.y;
            Kt[(c4 + 2) * 64 + r] = t4.z;
            Kt[(c4 + 3) * 64 + r] = t4.w;
            float4 v4 = *(const float4*)(vp + (size_t)r * (NKV * HD) + c4);
            *(float4*)&Vs[r * HD + c4] = v4;
        }
        __syncthreads();

        // S = Q K^T  (4x4 per thread)
        float s[4][4];
#pragma unroll
        for (int i = 0; i < 4; i++)
#pragma unroll
            for (int j = 0; j < 4; j++) s[i][j] = 0.f;

#pragma unroll 4
        for (int d = 0; d < HD; d++) {
            float4 qa = *(const float4*)&Qt[d * 64 + ty * 4];
            float4 kb = *(const float4*)&Kt[d * 64 + tx * 4];
            float ar[4] = {qa.x, qa.y, qa.z, qa.w};
            float br[4] = {kb.x, kb.y, kb.z, kb.w};
#pragma unroll
            for (int i = 0; i < 4; i++)
#pragma unroll
                for (int j = 0; j < 4; j++)
                    s[i][j] += ar[i] * br[j];
        }

        // scale + causal mask (only the diagonal tile can be partial)
        const bool diag = (kt == qb);
#pragma unroll
        for (int i = 0; i < 4; i++) {
            int qr = q0 + ty * 4 + i;
#pragma unroll
            for (int j = 0; j < 4; j++) {
                float val = s[i][j] * scale;
                if (diag && (kb0 + tx * 4 + j > qr)) val = -1e30f;
                s[i][j] = val;
            }
        }

        // Online softmax (row stats shared across 16 lanes of each ty group)
#pragma unroll
        for (int i = 0; i < 4; i++) {
            float mloc = fmaxf(fmaxf(s[i][0], s[i][1]), fmaxf(s[i][2], s[i][3]));
#pragma unroll
            for (int off = 8; off > 0; off >>= 1)
                mloc = fmaxf(mloc, __shfl_xor_sync(0xffffffffu, mloc, off, 16));
            float mnew  = fmaxf(m_i[i], mloc);
            float alpha = __expf(m_i[i] - mnew);
            float psum  = 0.f;
#pragma unroll
            for (int j = 0; j < 4; j++) {
                float p = __expf(s[i][j] - mnew);
                s[i][j] = p;
                psum += p;
            }
#pragma unroll
            for (int off = 8; off > 0; off >>= 1)
                psum += __shfl_xor_sync(0xffffffffu, psum, off, 16);
            l_i[i] = l_i[i] * alpha + psum;
            m_i[i] = mnew;
#pragma unroll
            for (int u = 0; u < 8; u++) acc[i][u] *= alpha;
        }

        // stage P in smem
#pragma unroll
        for (int i = 0; i < 4; i++)
#pragma unroll
            for (int j = 0; j < 4; j++)
                Ps[(ty * 4 + i) * PS_STRIDE + tx * 4 + j] = s[i][j];
        __syncthreads();

        // O += P @ V   (4 rows x 8 d-cols per thread)
#pragma unroll 2
        for (int j = 0; j < 64; j++) {
            float4 v0 = *(const float4*)&Vs[j * HD + tx * 8];
            float4 v1 = *(const float4*)&Vs[j * HD + tx * 8 + 4];
#pragma unroll
            for (int i = 0; i < 4; i++) {
                float p = Ps[(ty * 4 + i) * PS_STRIDE + j];
                acc[i][0] += p * v0.x; acc[i][1] += p * v0.y;
                acc[i][2] += p * v0.z; acc[i][3] += p * v0.w;
                acc[i][4] += p * v1.x; acc[i][5] += p * v1.y;
                acc[i][6] += p * v1.z; acc[i][7] += p * v1.w;
            }
        }
    }

    // Normalize & write O[b, qr, h, d]
#pragma unroll
    for (int i = 0; i < 4; i++) {
        int qr = q0 + ty * 4 + i;
        float inv = 1.f / l_i[i];
        float* op = o + ((size_t)(b * T_SEQ + qr) * NH + h) * HD + tx * 8;
        float4 o0, o1;
        o0.x = acc[i][0] * inv; o0.y = acc[i][1] * inv;
        o0.z = acc[i][2] * inv; o0.w = acc[i][3] * inv;
        o1.x = acc[i][4] * inv; o1.y = acc[i][5] * inv;
        o1.z = acc[i][6] * inv; o1.w = acc[i][7] * inv;
        *(float4*)op       = o0;
        *(float4*)(op + 4) = o1;
    }
}

// ---------------------------------------------------------------------------
extern "C" void kernel_launch(void* const* d_in, const int* in_sizes, int n_in,
                              void* d_out, int out_size)
{
    (void)in_sizes; (void)n_in; (void)out_size;
    const float* x    = (const float*)d_in[0];
    const float* cosT = (const float*)d_in[1];
    const float* sinT = (const float*)d_in[2];
    const float* wq   = (const float*)d_in[3];
    const float* wqb  = (const float*)d_in[4];
    const float* wk   = (const float*)d_in[5];
    const float* wkb  = (const float*)d_in[6];
    const float* wv   = (const float*)d_in[7];
    const float* wvb  = (const float*)d_in[8];
    const float* wo   = (const float*)d_in[9];
    float* out = (float*)d_out;

    float *qp, *kp, *vp, *ap;
    cudaGetSymbolAddress((void**)&qp, g_q);
    cudaGetSymbolAddress((void**)&kp, g_k);
    cudaGetSymbolAddress((void**)&vp, g_v);
    cudaGetSymbolAddress((void**)&ap, g_attn);

    const int M = NB * T_SEQ;  // 4096
    dim3 blk(256);

    // QKV projections
    sgemm_bias_kernel<<<dim3(DIM / 128, M / 128), blk>>>(x, wq, wqb, qp, M, DIM, DIM);
    sgemm_bias_kernel<<<dim3((NKV * HD) / 128, M / 128), blk>>>(x, wk, wkb, kp, M, NKV * HD, DIM);
    sgemm_bias_kernel<<<dim3((NKV * HD) / 128, M / 128), blk>>>(x, wv, wvb, vp, M, NKV * HD, DIM);

    // RoPE
    rope_kernel<<<(NB * T_SEQ * (NH + NKV) * 64) / 256, 256>>>(qp, kp, cosT, sinT);

    // Attention
    size_t smem = (size_t)(HD * 64 * 2 + 64 * HD + 64 * PS_STRIDE) * sizeof(float);
    cudaFuncSetAttribute(attn_kernel, cudaFuncAttributeMaxDynamicSharedMemorySize, (int)smem);
    attn_kernel<<<dim3(T_SEQ / 64, NH, NB), blk, smem>>>(qp, kp, vp, ap);

    // Output projection
    sgemm_bias_kernel<<<dim3(DIM / 128, M / 128), blk>>>(ap, wo, nullptr, out, M, DIM, DIM);
}

// round 2
// speedup vs baseline: 1.4953x; 1.4953x over previous
#include <cuda_runtime.h>
#include <cstdint>

#define T_SEQ 2048
#define NB    2
#define NH    16
#define NKV   2
#define HD    128
#define DIM   2048

// Scratch (allocation-free rule: __device__ globals)
__device__ float g_q[NB * T_SEQ * DIM];          // [B,T,16,128]
__device__ float g_k[NB * T_SEQ * NKV * HD];     // [B,T,2,128]
__device__ float g_v[NB * T_SEQ * NKV * HD];     // [B,T,2,128]
__device__ float g_attn[NB * T_SEQ * DIM];       // [B,T,16,128]

// ---------------------------------------------------------------------------
// tf32 helpers
// ---------------------------------------------------------------------------
__device__ __forceinline__ uint32_t f2tf(float f) {
    uint32_t u;
    asm("cvt.rna.tf32.f32 %0, %1;" : "=r"(u) : "f"(f));
    return u;
}

__device__ __forceinline__ void mma_tf32(float* c, const uint32_t* a, const uint32_t* b) {
    asm volatile(
        "mma.sync.aligned.m16n8k8.row.col.f32.tf32.tf32.f32 "
        "{%0,%1,%2,%3}, {%4,%5,%6,%7}, {%8,%9}, {%0,%1,%2,%3};\n"
        : "+f"(c[0]), "+f"(c[1]), "+f"(c[2]), "+f"(c[3])
        : "r"(a[0]), "r"(a[1]), "r"(a[2]), "r"(a[3]),
          "r"(b[0]), "r"(b[1]));
}

// ---------------------------------------------------------------------------
// TF32 GEMM: C[M,N] = A[M,K] @ B[K,N] (+ bias).  BM=BN=128, BK=16.
// 256 threads = 8 warps (2 along M x 4 along N); warp tile 64x32.
// smem k-major with stride 136 (k-stride = 8 banks -> conflict-free frags).
// ---------------------------------------------------------------------------
#define BM 128
#define BN 128
#define BKG 16
#define SST 136

__global__ __launch_bounds__(256)
void gemm_tf32_kernel(const float* __restrict__ A,
                      const float* __restrict__ Bw,
                      const float* __restrict__ bias,
                      float* __restrict__ C,
                      int M, int N, int K)
{
    __shared__ uint32_t As[BKG][SST];   // [k][m]
    __shared__ uint32_t Bs[BKG][SST];   // [k][n]

    const int tid  = threadIdx.x;
    const int lane = tid & 31;
    const int g    = lane >> 2;          // groupID 0..7
    const int tig  = lane & 3;           // thread-in-group 0..3
    const int warpId = tid >> 5;
    const int warpM  = warpId & 1;       // 2 warps along M
    const int warpN  = warpId >> 1;      // 4 warps along N
    const int mBase  = warpM * 64;
    const int nBase  = warpN * 32;

    const int rowBase = blockIdx.y * BM;
    const int colBase = blockIdx.x * BN;

    // global load mapping
    const int aRow = tid & 127;          // 0..127
    const int aK   = (tid >> 7) * 8;     // 0 or 8
    const int bK   = tid >> 5;           // 0..7  (and +8)
    const int bN   = (tid & 31) * 4;     // 0..124

    const float* Aptr = A  + (size_t)(rowBase + aRow) * K;
    const float* Bptr = Bw + colBase + bN;

    float acc[4][4][4];
#pragma unroll
    for (int mt = 0; mt < 4; mt++)
#pragma unroll
        for (int nt = 0; nt < 4; nt++)
#pragma unroll
            for (int i = 0; i < 4; i++) acc[mt][nt][i] = 0.f;

    // prefetch tile 0
    float4 pa0 = *(const float4*)(Aptr + aK);
    float4 pa1 = *(const float4*)(Aptr + aK + 4);
    float4 pb0 = *(const float4*)(Bptr + (size_t)bK * N);
    float4 pb1 = *(const float4*)(Bptr + (size_t)(bK + 8) * N);

    for (int k0 = 0; k0 < K; k0 += BKG) {
        // stage (with tf32 rounding)
        As[aK + 0][aRow] = f2tf(pa0.x);
        As[aK + 1][aRow] = f2tf(pa0.y);
        As[aK + 2][aRow] = f2tf(pa0.z);
        As[aK + 3][aRow] = f2tf(pa0.w);
        As[aK + 4][aRow] = f2tf(pa1.x);
        As[aK + 5][aRow] = f2tf(pa1.y);
        As[aK + 6][aRow] = f2tf(pa1.z);
        As[aK + 7][aRow] = f2tf(pa1.w);
        uint4 u0 = { f2tf(pb0.x), f2tf(pb0.y), f2tf(pb0.z), f2tf(pb0.w) };
        uint4 u1 = { f2tf(pb1.x), f2tf(pb1.y), f2tf(pb1.z), f2tf(pb1.w) };
        *(uint4*)&Bs[bK][bN]     = u0;
        *(uint4*)&Bs[bK + 8][bN] = u1;
        __syncthreads();

        // prefetch next tile
        if (k0 + BKG < K) {
            const float* An = Aptr + k0 + BKG;
            const float* Bn = Bptr + (size_t)(k0 + BKG) * N;
            pa0 = *(const float4*)(An + aK);
            pa1 = *(const float4*)(An + aK + 4);
            pb0 = *(const float4*)(Bn + (size_t)bK * N);
            pb1 = *(const float4*)(Bn + (size_t)(bK + 8) * N);
        }

        // compute: 2 k-steps of 8
#pragma unroll
        for (int kk = 0; kk < BKG; kk += 8) {
            uint32_t af[4][4], bf[4][2];
#pragma unroll
            for (int mt = 0; mt < 4; mt++) {
                int m = mBase + mt * 16 + g;
                af[mt][0] = As[kk + tig][m];
                af[mt][1] = As[kk + tig][m + 8];
                af[mt][2] = As[kk + tig + 4][m];
                af[mt][3] = As[kk + tig + 4][m + 8];
            }
#pragma unroll
            for (int nt = 0; nt < 4; nt++) {
                int n = nBase + nt * 8 + g;
                bf[nt][0] = Bs[kk + tig][n];
                bf[nt][1] = Bs[kk + tig + 4][n];
            }
#pragma unroll
            for (int mt = 0; mt < 4; mt++)
#pragma unroll
                for (int nt = 0; nt < 4; nt++)
                    mma_tf32(acc[mt][nt], af[mt], bf[nt]);
        }
        __syncthreads();
    }

    // epilogue: c0 (g, 2*tig), c1 (g, 2*tig+1), c2 (g+8, 2*tig), c3 (g+8, 2*tig+1)
#pragma unroll
    for (int mt = 0; mt < 4; mt++) {
#pragma unroll
        for (int half = 0; half < 2; half++) {
            int r = rowBase + mBase + mt * 16 + g + half * 8;
#pragma unroll
            for (int nt = 0; nt < 4; nt++) {
                int c = colBase + nBase + nt * 8 + tig * 2;
                float2 v;
                v.x = acc[mt][nt][half * 2 + 0];
                v.y = acc[mt][nt][half * 2 + 1];
                if (bias) { v.x += bias[c]; v.y += bias[c + 1]; }
                *(float2*)(C + (size_t)r * N + c) = v;
            }
        }
    }
}

// ---------------------------------------------------------------------------
// RoPE in-place on q [B,T,16,128] and k [B,T,2,128].
// ---------------------------------------------------------------------------
__global__ void rope_kernel(float* __restrict__ q, float* __restrict__ k,
                            const float* __restrict__ cosT,
                            const float* __restrict__ sinT)
{
    int idx = blockIdx.x * blockDim.x + threadIdx.x;
    int i   = idx & 63;  idx >>= 6;
    int h   = idx % 18;  idx /= 18;
    int t   = idx % T_SEQ;
    int b   = idx / T_SEQ;
    if (b >= NB) return;

    float c0 = cosT[t * HD + i];
    float s0 = sinT[t * HD + i];
    float c1 = cosT[t * HD + i + 64];
    float s1 = sinT[t * HD + i + 64];

    float* base;
    if (h < NH) base = q + ((size_t)(b * T_SEQ + t) * NH  + h)        * HD;
    else        base = k + ((size_t)(b * T_SEQ + t) * NKV + (h - NH)) * HD;

    float x1 = base[i];
    float x2 = base[i + 64];
    base[i]      = x1 * c0 - x2 * s0;
    base[i + 64] = x2 * c1 + x1 * s1;
}

// ---------------------------------------------------------------------------
// Flash attention fp32 (unchanged from round 1).
// ---------------------------------------------------------------------------
#define PS_STRIDE 68

__global__ void attn_kernel(const float* __restrict__ q,
                            const float* __restrict__ k,
                            const float* __restrict__ v,
                            float* __restrict__ o)
{
    extern __shared__ float sm[];
    float* Qt = sm;                   // [128][64]
    float* Kt = Qt + HD * 64;         // [128][64]
    float* Vs = Kt + HD * 64;         // [64][128]
    float* Ps = Vs + 64 * HD;         // [64][PS_STRIDE]

    const int qb  = blockIdx.x;
    const int h   = blockIdx.y;
    const int b   = blockIdx.z;
    const int kvh = h >> 3;
    const int tid = threadIdx.x;
    const int tx  = tid & 15;
    const int ty  = tid >> 4;
    const int q0  = qb * 64;
    const float scale = 0.0883883476483184405f;

    const float* qp = q + ((size_t)(b * T_SEQ + q0) * NH + h) * HD;
#pragma unroll
    for (int it = 0; it < 8; it++) {
        int lin = tid + it * 256;
        int r   = lin >> 5;
        int c4  = (lin & 31) << 2;
        float4 t4 = *(const float4*)(qp + (size_t)r * DIM + c4);
        Qt[(c4 + 0) * 64 + r] = t4.x;
        Qt[(c4 + 1) * 64 + r] = t4.y;
        Qt[(c4 + 2) * 64 + r] = t4.z;
        Qt[(c4 + 3) * 64 + r] = t4.w;
    }

    float m_i[4], l_i[4], acc[4][8];
#pragma unroll
    for (int i = 0; i < 4; i++) {
        m_i[i] = -1e30f; l_i[i] = 0.f;
#pragma unroll
        for (int u = 0; u < 8; u++) acc[i][u] = 0.f;
    }

    for (int kt = 0; kt <= qb; kt++) {
        const int kb0 = kt * 64;
        __syncthreads();

        const float* kp = k + ((size_t)(b * T_SEQ + kb0) * NKV + kvh) * HD;
        const float* vp = v + ((size_t)(b * T_SEQ + kb0) * NKV + kvh) * HD;
#pragma unroll
        for (int it = 0; it < 8; it++) {
            int lin = tid + it * 256;
            int r   = lin >> 5;
            int c4  = (lin & 31) << 2;
            float4 t4 = *(const float4*)(kp + (size_t)r * (NKV * HD) + c4);
            Kt[(c4 + 0) * 64 + r] = t4.x;
            Kt[(c4 + 1) * 64 + r] = t4.y;
            Kt[(c4 + 2) * 64 + r] = t4.z;
            Kt[(c4 + 3) * 64 + r] = t4.w;
            float4 v4 = *(const float4*)(vp + (size_t)r * (NKV * HD) + c4);
            *(float4*)&Vs[r * HD + c4] = v4;
        }
        __syncthreads();

        float s[4][4];
#pragma unroll
        for (int i = 0; i < 4; i++)
#pragma unroll
            for (int j = 0; j < 4; j++) s[i][j] = 0.f;

#pragma unroll 4
        for (int d = 0; d < HD; d++) {
            float4 qa = *(const float4*)&Qt[d * 64 + ty * 4];
            float4 kb = *(const float4*)&Kt[d * 64 + tx * 4];
            float ar[4] = {qa.x, qa.y, qa.z, qa.w};
            float br[4] = {kb.x, kb.y, kb.z, kb.w};
#pragma unroll
            for (int i = 0; i < 4; i++)
#pragma unroll
                for (int j = 0; j < 4; j++)
                    s[i][j] += ar[i] * br[j];
        }

        const bool diag = (kt == qb);
#pragma unroll
        for (int i = 0; i < 4; i++) {
            int qr = q0 + ty * 4 + i;
#pragma unroll
            for (int j = 0; j < 4; j++) {
                float val = s[i][j] * scale;
                if (diag && (kb0 + tx * 4 + j > qr)) val = -1e30f;
                s[i][j] = val;
            }
        }

#pragma unroll
        for (int i = 0; i < 4; i++) {
            float mloc = fmaxf(fmaxf(s[i][0], s[i][1]), fmaxf(s[i][2], s[i][3]));
#pragma unroll
            for (int off = 8; off > 0; off >>= 1)
                mloc = fmaxf(mloc, __shfl_xor_sync(0xffffffffu, mloc, off, 16));
            float mnew  = fmaxf(m_i[i], mloc);
            float alpha = __expf(m_i[i] - mnew);
            float psum  = 0.f;
#pragma unroll
            for (int j = 0; j < 4; j++) {
                float p = __expf(s[i][j] - mnew);
                s[i][j] = p;
                psum += p;
            }
#pragma unroll
            for (int off = 8; off > 0; off >>= 1)
                psum += __shfl_xor_sync(0xffffffffu, psum, off, 16);
            l_i[i] = l_i[i] * alpha + psum;
            m_i[i] = mnew;
#pragma unroll
            for (int u = 0; u < 8; u++) acc[i][u] *= alpha;
        }

#pragma unroll
        for (int i = 0; i < 4; i++)
#pragma unroll
            for (int j = 0; j < 4; j++)
                Ps[(ty * 4 + i) * PS_STRIDE + tx * 4 + j] = s[i][j];
        __syncthreads();

#pragma unroll 2
        for (int j = 0; j < 64; j++) {
            float4 v0 = *(const float4*)&Vs[j * HD + tx * 8];
            float4 v1 = *(const float4*)&Vs[j * HD + tx * 8 + 4];
#pragma unroll
            for (int i = 0; i < 4; i++) {
                float p = Ps[(ty * 4 + i) * PS_STRIDE + j];
                acc[i][0] += p * v0.x; acc[i][1] += p * v0.y;
                acc[i][2] += p * v0.z; acc[i][3] += p * v0.w;
                acc[i][4] += p * v1.x; acc[i][5] += p * v1.y;
                acc[i][6] += p * v1.z; acc[i][7] += p * v1.w;
            }
        }
    }

#pragma unroll
    for (int i = 0; i < 4; i++) {
        int qr = q0 + ty * 4 + i;
        float inv = 1.f / l_i[i];
        float* op = o + ((size_t)(b * T_SEQ + qr) * NH + h) * HD + tx * 8;
        float4 o0, o1;
        o0.x = acc[i][0] * inv; o0.y = acc[i][1] * inv;
        o0.z = acc[i][2] * inv; o0.w = acc[i][3] * inv;
        o1.x = acc[i][4] * inv; o1.y = acc[i][5] * inv;
        o1.z = acc[i][6] * inv; o1.w = acc[i][7] * inv;
        *(float4*)op       = o0;
        *(float4*)(op + 4) = o1;
    }
}

// ---------------------------------------------------------------------------
extern "C" void kernel_launch(void* const* d_in, const int* in_sizes, int n_in,
                              void* d_out, int out_size)
{
    (void)in_sizes; (void)n_in; (void)out_size;
    const float* x    = (const float*)d_in[0];
    const float* cosT = (const float*)d_in[1];
    const float* sinT = (const float*)d_in[2];
    const float* wq   = (const float*)d_in[3];
    const float* wqb  = (const float*)d_in[4];
    const float* wk   = (const float*)d_in[5];
    const float* wkb  = (const float*)d_in[6];
    const float* wv   = (const float*)d_in[7];
    const float* wvb  = (const float*)d_in[8];
    const float* wo   = (const float*)d_in[9];
    float* out = (float*)d_out;

    float *qp, *kp, *vp, *ap;
    cudaGetSymbolAddress((void**)&qp, g_q);
    cudaGetSymbolAddress((void**)&kp, g_k);
    cudaGetSymbolAddress((void**)&vp, g_v);
    cudaGetSymbolAddress((void**)&ap, g_attn);

    const int M = NB * T_SEQ;  // 4096
    dim3 blk(256);

    // QKV projections (tf32 tensor cores)
    gemm_tf32_kernel<<<dim3(DIM / 128, M / 128), blk>>>(x, wq, wqb, qp, M, DIM, DIM);
    gemm_tf32_kernel<<<dim3((NKV * HD) / 128, M / 128), blk>>>(x, wk, wkb, kp, M, NKV * HD, DIM);
    gemm_tf32_kernel<<<dim3((NKV * HD) / 128, M / 128), blk>>>(x, wv, wvb, vp, M, NKV * HD, DIM);

    // RoPE
    rope_kernel<<<(NB * T_SEQ * (NH + NKV) * 64) / 256, 256>>>(qp, kp, cosT, sinT);

    // Attention (fp32 SIMT — round-2 target)
    size_t smem = (size_t)(HD * 64 * 2 + 64 * HD + 64 * PS_STRIDE) * sizeof(float);
    cudaFuncSetAttribute(attn_kernel, cudaFuncAttributeMaxDynamicSharedMemorySize, (int)smem);
    attn_kernel<<<dim3(T_SEQ / 64, NH, NB), blk, smem>>>(qp, kp, vp, ap);

    // Output projection (tf32 tensor cores)
    gemm_tf32_kernel<<<dim3(DIM / 128, M / 128), blk>>>(ap, wo, nullptr, out, M, DIM, DIM);
}

// round 3
// speedup vs baseline: 2.9454x; 1.9698x over previous
#include <cuda_runtime.h>
#include <cstdint>

#define T_SEQ 2048
#define NB    2
#define NH    16
#define NKV   2
#define HD    128
#define DIM   2048

// Scratch (allocation-free rule: __device__ globals)
__device__ float g_q[NB * T_SEQ * DIM];          // [B,T,16,128]
__device__ float g_k[NB * T_SEQ * NKV * HD];     // [B,T,2,128]
__device__ float g_v[NB * T_SEQ * NKV * HD];     // [B,T,2,128]
__device__ float g_attn[NB * T_SEQ * DIM];       // [B,T,16,128]

// ---------------------------------------------------------------------------
// tf32 helpers
// ---------------------------------------------------------------------------
__device__ __forceinline__ uint32_t f2tf(float f) {
    uint32_t u;
    asm("cvt.rna.tf32.f32 %0, %1;" : "=r"(u) : "f"(f));
    return u;
}

__device__ __forceinline__ void mma_tf32(float* c, const uint32_t* a, const uint32_t* b) {
    asm volatile(
        "mma.sync.aligned.m16n8k8.row.col.f32.tf32.tf32.f32 "
        "{%0,%1,%2,%3}, {%4,%5,%6,%7}, {%8,%9}, {%0,%1,%2,%3};\n"
        : "+f"(c[0]), "+f"(c[1]), "+f"(c[2]), "+f"(c[3])
        : "r"(a[0]), "r"(a[1]), "r"(a[2]), "r"(a[3]),
          "r"(b[0]), "r"(b[1]));
}

// ---------------------------------------------------------------------------
// TF32 GEMM: C[M,N] = A[M,K] @ B[K,N] (+ bias).  BM=BN=128, BK=16.
// ---------------------------------------------------------------------------
#define BM 128
#define BN 128
#define BKG 16
#define SST 136

__global__ __launch_bounds__(256)
void gemm_tf32_kernel(const float* __restrict__ A,
                      const float* __restrict__ Bw,
                      const float* __restrict__ bias,
                      float* __restrict__ C,
                      int M, int N, int K)
{
    __shared__ uint32_t As[BKG][SST];   // [k][m]
    __shared__ uint32_t Bs[BKG][SST];   // [k][n]

    const int tid  = threadIdx.x;
    const int lane = tid & 31;
    const int g    = lane >> 2;
    const int tig  = lane & 3;
    const int warpId = tid >> 5;
    const int warpM  = warpId & 1;
    const int warpN  = warpId >> 1;
    const int mBase  = warpM * 64;
    const int nBase  = warpN * 32;

    const int rowBase = blockIdx.y * BM;
    const int colBase = blockIdx.x * BN;

    const int aRow = tid & 127;
    const int aK   = (tid >> 7) * 8;
    const int bK   = tid >> 5;
    const int bN   = (tid & 31) * 4;

    const float* Aptr = A  + (size_t)(rowBase + aRow) * K;
    const float* Bptr = Bw + colBase + bN;

    float acc[4][4][4];
#pragma unroll
    for (int mt = 0; mt < 4; mt++)
#pragma unroll
        for (int nt = 0; nt < 4; nt++)
#pragma unroll
            for (int i = 0; i < 4; i++) acc[mt][nt][i] = 0.f;

    float4 pa0 = *(const float4*)(Aptr + aK);
    float4 pa1 = *(const float4*)(Aptr + aK + 4);
    float4 pb0 = *(const float4*)(Bptr + (size_t)bK * N);
    float4 pb1 = *(const float4*)(Bptr + (size_t)(bK + 8) * N);

    for (int k0 = 0; k0 < K; k0 += BKG) {
        As[aK + 0][aRow] = f2tf(pa0.x);
        As[aK + 1][aRow] = f2tf(pa0.y);
        As[aK + 2][aRow] = f2tf(pa0.z);
        As[aK + 3][aRow] = f2tf(pa0.w);
        As[aK + 4][aRow] = f2tf(pa1.x);
        As[aK + 5][aRow] = f2tf(pa1.y);
        As[aK + 6][aRow] = f2tf(pa1.z);
        As[aK + 7][aRow] = f2tf(pa1.w);
        uint4 u0 = { f2tf(pb0.x), f2tf(pb0.y), f2tf(pb0.z), f2tf(pb0.w) };
        uint4 u1 = { f2tf(pb1.x), f2tf(pb1.y), f2tf(pb1.z), f2tf(pb1.w) };
        *(uint4*)&Bs[bK][bN]     = u0;
        *(uint4*)&Bs[bK + 8][bN] = u1;
        __syncthreads();

        if (k0 + BKG < K) {
            const float* An = Aptr + k0 + BKG;
            const float* Bn = Bptr + (size_t)(k0 + BKG) * N;
            pa0 = *(const float4*)(An + aK);
            pa1 = *(const float4*)(An + aK + 4);
            pb0 = *(const float4*)(Bn + (size_t)bK * N);
            pb1 = *(const float4*)(Bn + (size_t)(bK + 8) * N);
        }

#pragma unroll
        for (int kk = 0; kk < BKG; kk += 8) {
            uint32_t af[4][4], bf[4][2];
#pragma unroll
            for (int mt = 0; mt < 4; mt++) {
                int m = mBase + mt * 16 + g;
                af[mt][0] = As[kk + tig][m];
                af[mt][1] = As[kk + tig][m + 8];
                af[mt][2] = As[kk + tig + 4][m];
                af[mt][3] = As[kk + tig + 4][m + 8];
            }
#pragma unroll
            for (int nt = 0; nt < 4; nt++) {
                int n = nBase + nt * 8 + g;
                bf[nt][0] = Bs[kk + tig][n];
                bf[nt][1] = Bs[kk + tig + 4][n];
            }
#pragma unroll
            for (int mt = 0; mt < 4; mt++)
#pragma unroll
                for (int nt = 0; nt < 4; nt++)
                    mma_tf32(acc[mt][nt], af[mt], bf[nt]);
        }
        __syncthreads();
    }

#pragma unroll
    for (int mt = 0; mt < 4; mt++) {
#pragma unroll
        for (int half = 0; half < 2; half++) {
            int r = rowBase + mBase + mt * 16 + g + half * 8;
#pragma unroll
            for (int nt = 0; nt < 4; nt++) {
                int c = colBase + nBase + nt * 8 + tig * 2;
                float2 v;
                v.x = acc[mt][nt][half * 2 + 0];
                v.y = acc[mt][nt][half * 2 + 1];
                if (bias) { v.x += bias[c]; v.y += bias[c + 1]; }
                *(float2*)(C + (size_t)r * N + c) = v;
            }
        }
    }
}

// ---------------------------------------------------------------------------
// RoPE in-place on q [B,T,16,128] and k [B,T,2,128].
// ---------------------------------------------------------------------------
__global__ void rope_kernel(float* __restrict__ q, float* __restrict__ k,
                            const float* __restrict__ cosT,
                            const float* __restrict__ sinT)
{
    int idx = blockIdx.x * blockDim.x + threadIdx.x;
    int i   = idx & 63;  idx >>= 6;
    int h   = idx % 18;  idx /= 18;
    int t   = idx % T_SEQ;
    int b   = idx / T_SEQ;
    if (b >= NB) return;

    float c0 = cosT[t * HD + i];
    float s0 = sinT[t * HD + i];
    float c1 = cosT[t * HD + i + 64];
    float s1 = sinT[t * HD + i + 64];

    float* base;
    if (h < NH) base = q + ((size_t)(b * T_SEQ + t) * NH  + h)        * HD;
    else        base = k + ((size_t)(b * T_SEQ + t) * NKV + (h - NH)) * HD;

    float x1 = base[i];
    float x2 = base[i + 64];
    base[i]      = x1 * c0 - x2 * s0;
    base[i + 64] = x2 * c1 + x1 * s1;
}

// ---------------------------------------------------------------------------
// Flash attention on tensor cores (tf32 mma.sync).
// BM=128 q rows/CTA, BN=64 keys/iter, 8 warps x 16 rows.
// Row-major smem, strides chosen so fragment gathers are bank-conflict-free:
//   Q/K/P stride ≡ 4 (mod 32); V stride ≡ 8 (mod 32).
// ---------------------------------------------------------------------------
#define QST 132
#define KST 132
#define VST 136
#define PST 68
#define ATTN_SMEM_WORDS (128*QST + 64*KST + 64*VST + 128*PST)

__global__ __launch_bounds__(256)
void attn_tc_kernel(const float* __restrict__ q,
                    const float* __restrict__ k,
                    const float* __restrict__ v,
                    float* __restrict__ o)
{
    extern __shared__ uint32_t sm[];
    uint32_t* Qs = sm;                 // [128][QST]
    uint32_t* Ks = Qs + 128 * QST;     // [64][KST]
    uint32_t* Vs = Ks + 64 * KST;      // [64][VST]
    uint32_t* Ps = Vs + 64 * VST;      // [128][PST]

    const int qb   = blockIdx.x;
    const int h    = blockIdx.y;
    const int b    = blockIdx.z;
    const int kvh  = h >> 3;
    const int tid  = threadIdx.x;
    const int lane = tid & 31;
    const int warp = tid >> 5;
    const int g    = lane >> 2;
    const int tig  = lane & 3;
    const int q0   = qb * 128;
    const int row0 = warp * 16;
    const float scale = 0.0883883476483184405f;   // 1/sqrt(128)

    // ---- Load Q tile [128 rows][128 d] into smem (tf32), coalesced ----
    const float* qp = q + ((size_t)(b * T_SEQ + q0) * NH + h) * HD;
#pragma unroll
    for (int it = 0; it < 16; it++) {
        int idx = tid + it * 256;          // float4 index 0..4095
        int r   = idx >> 5;
        int c4  = (idx & 31) << 2;
        float4 t = *(const float4*)(qp + (size_t)r * DIM + c4);
        uint4 u = { f2tf(t.x), f2tf(t.y), f2tf(t.z), f2tf(t.w) };
        *(uint4*)&Qs[r * QST + c4] = u;
    }

    float m_r[2] = { -1e30f, -1e30f };
    float l_r[2] = { 0.f, 0.f };
    float o_acc[16][4];
#pragma unroll
    for (int nt = 0; nt < 16; nt++)
#pragma unroll
        for (int e = 0; e < 4; e++) o_acc[nt][e] = 0.f;

    const int nkt = 2 * qb + 2;
    for (int kt = 0; kt < nkt; kt++) {
        const int kb0 = kt * 64;
        __syncthreads();   // prev-iter PV readers done before overwriting K/V

        // ---- Load K,V tiles [64 keys][128 d] (tf32) ----
        const float* kp = k + ((size_t)(b * T_SEQ + kb0) * NKV + kvh) * HD;
        const float* vp = v + ((size_t)(b * T_SEQ + kb0) * NKV + kvh) * HD;
#pragma unroll
        for (int it = 0; it < 8; it++) {
            int idx = tid + it * 256;       // float4 index 0..2047
            int r   = idx >> 5;
            int c4  = (idx & 31) << 2;
            float4 tk = *(const float4*)(kp + (size_t)r * (NKV * HD) + c4);
            uint4 uk = { f2tf(tk.x), f2tf(tk.y), f2tf(tk.z), f2tf(tk.w) };
            *(uint4*)&Ks[r * KST + c4] = uk;
            float4 tv = *(const float4*)(vp + (size_t)r * (NKV * HD) + c4);
            uint4 uv = { f2tf(tv.x), f2tf(tv.y), f2tf(tv.z), f2tf(tv.w) };
            *(uint4*)&Vs[r * VST + c4] = uv;
        }
        __syncthreads();

        // ---- S = Q K^T : this warp -> rows [row0,row0+16) x 64 keys ----
        float s[8][4];
#pragma unroll
        for (int nt = 0; nt < 8; nt++)
#pragma unroll
            for (int e = 0; e < 4; e++) s[nt][e] = 0.f;

#pragma unroll
        for (int kk = 0; kk < HD; kk += 8) {
            uint32_t a[4];
            a[0] = Qs[(row0 + g) * QST + kk + tig];
            a[1] = Qs[(row0 + g + 8) * QST + kk + tig];
            a[2] = Qs[(row0 + g) * QST + kk + tig + 4];
            a[3] = Qs[(row0 + g + 8) * QST + kk + tig + 4];
#pragma unroll
            for (int nt = 0; nt < 8; nt++) {
                uint32_t bb[2];
                bb[0] = Ks[(nt * 8 + g) * KST + kk + tig];
                bb[1] = Ks[(nt * 8 + g) * KST + kk + tig + 4];
                mma_tf32(s[nt], a, bb);
            }
        }

        // ---- scale + causal mask (only last two tiles straddle diagonal) ----
        const bool maskt = (kt >= 2 * qb);
#pragma unroll
        for (int nt = 0; nt < 8; nt++)
#pragma unroll
            for (int e = 0; e < 4; e++) {
                int r = q0 + row0 + g + ((e >> 1) << 3);
                int c = kb0 + nt * 8 + 2 * tig + (e & 1);
                float val = s[nt][e] * scale;
                if (maskt && (c > r)) val = -1e30f;
                s[nt][e] = val;
            }

        // ---- online softmax per row-half (rows g and g+8) ----
#pragma unroll
        for (int half = 0; half < 2; half++) {
            float mloc = -1e30f;
#pragma unroll
            for (int nt = 0; nt < 8; nt++)
                mloc = fmaxf(mloc, fmaxf(s[nt][half * 2], s[nt][half * 2 + 1]));
            mloc = fmaxf(mloc, __shfl_xor_sync(0xffffffffu, mloc, 1));
            mloc = fmaxf(mloc, __shfl_xor_sync(0xffffffffu, mloc, 2));
            float mnew  = fmaxf(m_r[half], mloc);
            float alpha = __expf(m_r[half] - mnew);
            float psum  = 0.f;
#pragma unroll
            for (int nt = 0; nt < 8; nt++) {
                float p0 = __expf(s[nt][half * 2]     - mnew);
                float p1 = __expf(s[nt][half * 2 + 1] - mnew);
                s[nt][half * 2]     = p0;
                s[nt][half * 2 + 1] = p1;
                psum += p0 + p1;
            }
            psum += __shfl_xor_sync(0xffffffffu, psum, 1);
            psum += __shfl_xor_sync(0xffffffffu, psum, 2);
            l_r[half] = l_r[half] * alpha + psum;
            m_r[half] = mnew;
#pragma unroll
            for (int nt = 0; nt < 16; nt++) {
                o_acc[nt][half * 2]     *= alpha;
                o_acc[nt][half * 2 + 1] *= alpha;
            }
        }

        // ---- stage P (tf32) in smem; per-warp private rows ----
#pragma unroll
        for (int nt = 0; nt < 8; nt++) {
            int c = nt * 8 + 2 * tig;
            Ps[(row0 + g) * PST + c]         = f2tf(s[nt][0]);
            Ps[(row0 + g) * PST + c + 1]     = f2tf(s[nt][1]);
            Ps[(row0 + g + 8) * PST + c]     = f2tf(s[nt][2]);
            Ps[(row0 + g + 8) * PST + c + 1] = f2tf(s[nt][3]);
        }
        __syncwarp();

        // ---- O += P @ V : rows [row0,row0+16) x 128 d ----
#pragma unroll
        for (int kk = 0; kk < 64; kk += 8) {
            uint32_t a[4];
            a[0] = Ps[(row0 + g) * PST + kk + tig];
            a[1] = Ps[(row0 + g + 8) * PST + kk + tig];
            a[2] = Ps[(row0 + g) * PST + kk + tig + 4];
            a[3] = Ps[(row0 + g + 8) * PST + kk + tig + 4];
#pragma unroll
            for (int nt = 0; nt < 16; nt++) {
                uint32_t bb[2];
                bb[0] = Vs[(kk + tig) * VST + nt * 8 + g];
                bb[1] = Vs[(kk + tig + 4) * VST + nt * 8 + g];
                mma_tf32(o_acc[nt], a, bb);
            }
        }
    }

    // ---- normalize & write O[b, q0+row, h, d] ----
    const float inv0 = 1.f / l_r[0];
    const float inv1 = 1.f / l_r[1];
    float* op = o + ((size_t)(b * T_SEQ + q0) * NH + h) * HD;
#pragma unroll
    for (int nt = 0; nt < 16; nt++) {
        int c = nt * 8 + 2 * tig;
        float2 v0 = { o_acc[nt][0] * inv0, o_acc[nt][1] * inv0 };
        float2 v1 = { o_acc[nt][2] * inv1, o_acc[nt][3] * inv1 };
        *(float2*)(op + (size_t)(row0 + g) * DIM + c)     = v0;
        *(float2*)(op + (size_t)(row0 + g + 8) * DIM + c) = v1;
    }
}

// ---------------------------------------------------------------------------
extern "C" void kernel_launch(void* const* d_in, const int* in_sizes, int n_in,
                              void* d_out, int out_size)
{
    (void)in_sizes; (void)n_in; (void)out_size;
    const float* x    = (const float*)d_in[0];
    const float* cosT = (const float*)d_in[1];
    const float* sinT = (const float*)d_in[2];
    const float* wq   = (const float*)d_in[3];
    const float* wqb  = (const float*)d_in[4];
    const float* wk   = (const float*)d_in[5];
    const float* wkb  = (const float*)d_in[6];
    const float* wv   = (const float*)d_in[7];
    const float* wvb  = (const float*)d_in[8];
    const float* wo   = (const float*)d_in[9];
    float* out = (float*)d_out;

    float *qp, *kp, *vp, *ap;
    cudaGetSymbolAddress((void**)&qp, g_q);
    cudaGetSymbolAddress((void**)&kp, g_k);
    cudaGetSymbolAddress((void**)&vp, g_v);
    cudaGetSymbolAddress((void**)&ap, g_attn);

    const int M = NB * T_SEQ;  // 4096
    dim3 blk(256);

    // QKV projections (tf32 tensor cores)
    gemm_tf32_kernel<<<dim3(DIM / 128, M / 128), blk>>>(x, wq, wqb, qp, M, DIM, DIM);
    gemm_tf32_kernel<<<dim3((NKV * HD) / 128, M / 128), blk>>>(x, wk, wkb, kp, M, NKV * HD, DIM);
    gemm_tf32_kernel<<<dim3((NKV * HD) / 128, M / 128), blk>>>(x, wv, wvb, vp, M, NKV * HD, DIM);

    // RoPE
    rope_kernel<<<(NB * T_SEQ * (NH + NKV) * 64) / 256, 256>>>(qp, kp, cosT, sinT);

    // Attention on tensor cores
    size_t smem = (size_t)ATTN_SMEM_WORDS * sizeof(uint32_t);
    cudaFuncSetAttribute(attn_tc_kernel, cudaFuncAttributeMaxDynamicSharedMemorySize, (int)smem);
    attn_tc_kernel<<<dim3(T_SEQ / 128, NH, NB), blk, smem>>>(qp, kp, vp, ap);

    // Output projection (tf32 tensor cores)
    gemm_tf32_kernel<<<dim3(DIM / 128, M / 128), blk>>>(ap, wo, nullptr, out, M, DIM, DIM);
}